// round 1
// baseline (speedup 1.0000x reference)
#include <cuda_runtime.h>
#include <cuda_bf16.h>
#include <cstdint>

#define DD 64
#define HH 256
#define WW 256
#define NVOX (DD*HH*WW)
#define EPSF 1e-5f
#define FOUR_PI 12.566370614359172f

// ---- scratch (no allocations allowed) ----
__device__ int           g_parent[NVOX];
__device__ unsigned int  g_area[NVOX];
__device__ unsigned int  g_perim[NVOX];
__device__ unsigned char g_fg[NVOX];
__device__ float         g_acc;

// coherent (L2) loads/stores for the concurrently-mutated parent array
__device__ __forceinline__ int pload(int i) { return __ldcg(&g_parent[i]); }
__device__ __forceinline__ void pstore(int i, int v) { __stcg(&g_parent[i], v); }

__device__ __forceinline__ int uf_find(int i) {
    while (true) {
        int p = pload(i);
        if (p == i) return i;
        int gp = pload(p);
        if (gp == p) return p;
        pstore(i, gp);        // path halving
        i = gp;
    }
}

__device__ __forceinline__ void uf_union(int a, int b) {
    int ra = uf_find(a);
    int rb = uf_find(b);
    while (ra != rb) {
        if (ra < rb) { int t = ra; ra = rb; rb = t; }   // link larger root under smaller
        int old = atomicCAS(&g_parent[ra], ra, rb);
        if (old == ra) return;
        ra = uf_find(old);
        rb = uf_find(rb);
    }
}

// ---------------- kernels ----------------

__global__ void k_init(const float* __restrict__ y) {
    int i = blockIdx.x * blockDim.x + threadIdx.x;
    bool f = y[i] > 0.5f;
    g_fg[i]     = f ? 1 : 0;
    g_parent[i] = f ? i : -1;
    g_area[i]   = 0u;
    g_perim[i]  = 0u;
    if (i == 0) g_acc = 0.0f;
}

__global__ void k_merge() {
    int i = blockIdx.x * blockDim.x + threadIdx.x;
    if (!g_fg[i]) return;
    int x = i & (WW - 1);
    int y = (i >> 8) & (HH - 1);
    int z = i >> 16;

    // 13 "forward" offsets of the 26-neighborhood
    const int off[13][3] = {
        {1,-1,-1},{1,-1,0},{1,-1,1},
        {1, 0,-1},{1, 0,0},{1, 0,1},
        {1, 1,-1},{1, 1,0},{1, 1,1},
        {0, 1,-1},{0, 1,0},{0, 1,1},
        {0, 0, 1}
    };
#pragma unroll
    for (int k = 0; k < 13; k++) {
        int nz = z + off[k][0];
        int ny = y + off[k][1];
        int nx = x + off[k][2];
        if ((unsigned)nz < DD && (unsigned)ny < HH && (unsigned)nx < WW) {
            int j = (nz << 16) | (ny << 8) | nx;
            if (g_fg[j]) uf_union(i, j);
        }
    }
}

__global__ void k_accum() {
    int i = blockIdx.x * blockDim.x + threadIdx.x;
    bool f = (g_fg[i] != 0);
    int r = -1;
    bool bnd = false;
    if (f) {
        r = uf_find(i);
        int x = i & (WW - 1);
        int y = (i >> 8) & (HH - 1);
        int z = i >> 16;
        // reflect padding (jnp.pad mode='reflect', pad=1)
        int zm = (z == 0)      ? 1      : z - 1;
        int zp = (z == DD - 1) ? DD - 2 : z + 1;
        int ym = (y == 0)      ? 1      : y - 1;
        int yp = (y == HH - 1) ? HH - 2 : y + 1;
        int xm = (x == 0)      ? 1      : x - 1;
        int xp = (x == WW - 1) ? WW - 2 : x + 1;
        int zz[3] = {zm, z, zp};
        int yy[3] = {ym, y, yp};
        int xx[3] = {xm, x, xp};
        bool all = true;
#pragma unroll
        for (int a = 0; a < 3; a++)
#pragma unroll
            for (int b = 0; b < 3; b++)
#pragma unroll
                for (int c = 0; c < 3; c++) {
                    int nz = (a != 1) + (b != 1) + (c != 1);
                    if (nz >= 1 && nz <= 2) {   // 18-connectivity
                        int j = (zz[a] << 16) | (yy[b] << 8) | xx[c];
                        all = all && (g_fg[j] != 0);
                    }
                }
        bnd = !all;   // fg & ~erosion(fg)
    }
    // warp-aggregated atomics keyed by root (giant component -> 32x fewer atomics)
    unsigned peers = __match_any_sync(0xffffffffu, r);
    unsigned bm    = __ballot_sync(0xffffffffu, bnd);
    int lane = threadIdx.x & 31;
    if (f && lane == (__ffs(peers) - 1)) {
        atomicAdd(&g_area[r], (unsigned)__popc(peers));
        unsigned pb = (unsigned)__popc(peers & bm);
        if (pb) atomicAdd(&g_perim[r], pb);
    }
}

__global__ void k_reduce() {
    int i = blockIdx.x * blockDim.x + threadIdx.x;
    if (g_fg[i] && __ldcg(&g_parent[i]) == i) {
        float a = (float)g_area[i];
        float p = (float)g_perim[i];
        atomicAdd(&g_acc, FOUR_PI * a / (p * p + EPSF));
    }
}

__global__ void k_final(float* __restrict__ out) {
    float comp = g_acc * (1.0f / (float)DD);
    out[0] = 1.0f / (comp + EPSF);
}

extern "C" void kernel_launch(void* const* d_in, const int* in_sizes, int n_in,
                              void* d_out, int out_size) {
    const float* y = (const float*)d_in[0];
    float* out = (float*)d_out;
    const int threads = 256;
    const int blocks = NVOX / threads;   // 16384

    k_init<<<blocks, threads>>>(y);
    k_merge<<<blocks, threads>>>();
    k_accum<<<blocks, threads>>>();
    k_reduce<<<blocks, threads>>>();
    k_final<<<1, 1>>>(out);
}

// round 2
// speedup vs baseline: 1.0240x; 1.0240x over previous
#include <cuda_runtime.h>
#include <cuda_bf16.h>
#include <cstdint>

#define DD 64
#define HH 256
#define WW 256
#define NVOX (DD*HH*WW)
#define NWORD (NVOX/32)          // 131072 ; 8 words per row, 2048 per z-plane
#define EPSF 1e-5f
#define FOUR_PI 12.566370614359172f

__device__ int           g_parent[NVOX];
__device__ unsigned int  g_area[NVOX];
__device__ unsigned int  g_perim[NVOX];
__device__ unsigned int  g_bits[NWORD];
__device__ unsigned int  g_bnd[NWORD];
__device__ float         g_acc;

__device__ __forceinline__ int pload(int i) { return __ldcg(&g_parent[i]); }
__device__ __forceinline__ void pstore(int i, int v) { __stcg(&g_parent[i], v); }

__device__ __forceinline__ int uf_find(int i) {
    while (true) {
        int p = pload(i);
        if (p == i) return i;
        int gp = pload(p);
        if (gp == p) return p;
        pstore(i, gp);          // path halving
        i = gp;
    }
}

__device__ __forceinline__ void uf_union(int a, int b) {
    int ra = uf_find(a);
    int rb = uf_find(b);
    while (ra != rb) {
        if (ra < rb) { int t = ra; ra = rb; rb = t; }   // link larger under smaller
        int old = atomicCAS(&g_parent[ra], ra, rb);
        if (old == ra) return;
        ra = uf_find(old);
        rb = uf_find(rb);
    }
}

// ---------------- kernels ----------------

__global__ void k_init(const float* __restrict__ y) {
    int i = blockIdx.x * blockDim.x + threadIdx.x;
    float v = y[i];
    bool f = v > 0.5f;
    unsigned w = __ballot_sync(0xffffffffu, f);
    int lane = threadIdx.x & 31;
    if (lane == 0) g_bits[i >> 5] = w;
    bool fl;
    if (lane > 0) fl = (w >> (lane - 1)) & 1u;
    else          fl = ((i & (WW - 1)) != 0) && (__ldg(&y[i - 1]) > 0.5f);
    g_parent[i] = (f && fl) ? i - 1 : i;     // pre-link x-runs
    g_area[i]  = 0u;
    g_perim[i] = 0u;
    if (i == 0) g_acc = 0.0f;
}

// load word k of row (ry,rz) with its left/right neighbors within the row
__device__ __forceinline__ void load3(int ry, int rz, int k,
                                      unsigned& c, unsigned& l, unsigned& r) {
    int rw = (rz << 11) + (ry << 3) + k;
    c = g_bits[rw];
    l = (k > 0) ? g_bits[rw - 1] : 0u;
    r = (k < 7) ? g_bits[rw + 1] : 0u;
}

// 18-neighborhood inner boundary, reflect padding; one thread per word
__global__ void k_bnd() {
    int w = blockIdx.x * blockDim.x + threadIdx.x;
    int k = w & 7;
    int row = w >> 3;
    int y = row & (HH - 1);
    int z = row >> 8;
    int ym = (y == 0)      ? 1      : y - 1;
    int yp = (y == HH - 1) ? HH - 2 : y + 1;
    int zm = (z == 0)      ? 1      : z - 1;
    int zp = (z == DD - 1) ? DD - 2 : z + 1;

    unsigned ero = 0xffffffffu;

    // rows contributing (center + shl + shr): (y,z) [shifts only], (ym,z),(yp,z),(y,zm),(y,zp)
    {
        unsigned c, l, r;
        load3(y, z, k, c, l, r);
        unsigned shl = (c << 1) | (l >> 31);
        unsigned shr = (c >> 1) | (r << 31);
        if (k == 0) shl |= (c >> 1) & 1u;                    // x reflect at 0
        if (k == 7) shr |= ((c >> 30) & 1u) << 31;           // x reflect at 255
        ero &= shl & shr;
        unsigned A = c;                                       // fg of this word
        // edge rows
        int eys[4] = { ym, yp, y,  y  };
        int ezs[4] = { z,  z,  zm, zp };
#pragma unroll
        for (int t = 0; t < 4; t++) {
            unsigned cc, ll, rr;
            load3(eys[t], ezs[t], k, cc, ll, rr);
            unsigned s1 = (cc << 1) | (ll >> 31);
            unsigned s2 = (cc >> 1) | (rr << 31);
            if (k == 0) s1 |= (cc >> 1) & 1u;
            if (k == 7) s2 |= ((cc >> 30) & 1u) << 31;
            ero &= cc & s1 & s2;
        }
        // corner rows (dx must be 0 for conn<=2): (ym,zm),(yp,zm),(ym,zp),(yp,zp)
        int cys[4] = { ym, yp, ym, yp };
        int czs[4] = { zm, zm, zp, zp };
#pragma unroll
        for (int t = 0; t < 4; t++) {
            int rw = (czs[t] << 11) + (cys[t] << 3) + k;
            ero &= g_bits[rw];
        }
        g_bnd[w] = A & ~ero;
    }
}

// run-pruned 26-connectivity unions; one thread per word
__global__ void k_merge() {
    int w = blockIdx.x * blockDim.x + threadIdx.x;
    unsigned A = g_bits[w];
    if (A == 0u) return;
    int k = w & 7;
    int row = w >> 3;
    int y = row & (HH - 1);
    int z = row >> 8;
    int base = w << 5;

    unsigned Al = (k > 0) ? g_bits[w - 1] : 0u;
    unsigned Ar = (k < 7) ? g_bits[w + 1] : 0u;
    unsigned shlA = (A << 1) | (Al >> 31);
    unsigned shrA = (A >> 1) | (Ar << 31);

    // unordered neighbor-row pairs: (dy,dz) in {(-1,0),(-1,-1),(0,-1),(1,-1)}
    const int dys[4] = { -1, -1, 0, 1 };
    const int dzs[4] = {  0, -1, -1, -1 };
#pragma unroll
    for (int t = 0; t < 4; t++) {
        int ny = y + dys[t];
        int nz = z + dzs[t];
        if ((unsigned)ny >= HH || (unsigned)nz >= DD) continue;
        int nw = w + dys[t] * 8 + dzs[t] * 2048;
        unsigned B  = g_bits[nw];
        unsigned Bl = (k > 0) ? g_bits[nw - 1] : 0u;
        unsigned Br = (k < 7) ? g_bits[nw + 1] : 0u;
        unsigned AB = A & B;
        unsigned ABl = Al & Bl;
        unsigned shlAB = (AB << 1) | (ABl >> 31);
        unsigned shlB  = (B << 1) | (Bl >> 31);
        unsigned shrB  = (B >> 1) | (Br << 31);

        unsigned Vn  = AB & ~shlAB;                     // link (p) - (p)
        unsigned DLn = A & ~shlA & shlB & ~B;           // link (p) - (p-1)
        unsigned DRn = A & ~shrA & shrB & ~B;           // link (p) - (p+1)

        int nbase = nw << 5;
        while (Vn)  { int p = __ffs(Vn)  - 1; Vn  &= Vn  - 1; uf_union(base + p, nbase + p); }
        while (DLn) { int p = __ffs(DLn) - 1; DLn &= DLn - 1; uf_union(base + p, nbase + p - 1); }
        while (DRn) { int p = __ffs(DRn) - 1; DRn &= DRn - 1; uf_union(base + p, nbase + p + 1); }
    }
}

__global__ void k_accum() {
    int i = blockIdx.x * blockDim.x + threadIdx.x;
    unsigned wb = g_bits[i >> 5];
    unsigned bb = g_bnd[i >> 5];
    int lane = i & 31;
    bool f   = (wb >> lane) & 1u;
    bool bnd = (bb >> lane) & 1u;
    int r = -1;
    if (f) r = uf_find(i);
    unsigned peers = __match_any_sync(0xffffffffu, r);
    unsigned bm    = __ballot_sync(0xffffffffu, bnd);
    if (f && (threadIdx.x & 31) == (__ffs(peers) - 1)) {
        atomicAdd(&g_area[r], (unsigned)__popc(peers));
        unsigned pb = (unsigned)__popc(peers & bm);
        if (pb) atomicAdd(&g_perim[r], pb);
    }
}

__global__ void k_reduce() {
    int i = blockIdx.x * blockDim.x + threadIdx.x;
    unsigned wb = g_bits[i >> 5];
    if (((wb >> (i & 31)) & 1u) && __ldcg(&g_parent[i]) == i) {
        float a = (float)g_area[i];
        float p = (float)g_perim[i];
        atomicAdd(&g_acc, FOUR_PI * a / (p * p + EPSF));
    }
}

__global__ void k_final(float* __restrict__ out) {
    float comp = g_acc * (1.0f / (float)DD);
    out[0] = 1.0f / (comp + EPSF);
}

extern "C" void kernel_launch(void* const* d_in, const int* in_sizes, int n_in,
                              void* d_out, int out_size) {
    const float* y = (const float*)d_in[0];
    float* out = (float*)d_out;
    const int threads = 256;

    k_init<<<NVOX / threads, threads>>>(y);
    k_bnd<<<NWORD / threads, threads>>>();
    k_merge<<<NWORD / threads, threads>>>();
    k_accum<<<NVOX / threads, threads>>>();
    k_reduce<<<NVOX / threads, threads>>>();
    k_final<<<1, 1>>>(out);
}

// round 3
// speedup vs baseline: 2.0315x; 1.9840x over previous
#include <cuda_runtime.h>
#include <cuda_bf16.h>
#include <cstdint>

#define DD 64
#define HH 256
#define WW 256
#define NVOX (DD*HH*WW)
#define NWORD (NVOX/32)          // 131072 ; 8 words/row, 2048 words/z-plane
#define EPSF 1e-5f
#define FOUR_PI 12.566370614359172f

// tile = 256(x) x 16(y) x 8(z) = 32768 voxels, 1024 words
#define TY 16
#define TZ 8
#define TVOX 32768
#define TWORDS 1024
#define SMEM_BYTES (TVOX*4 + TWORDS*4)

__device__ int           g_parent[NVOX];
__device__ unsigned int  g_area[NVOX];
__device__ unsigned int  g_perim[NVOX];
__device__ unsigned int  g_bits[NWORD];
__device__ unsigned int  g_bnd[NWORD];
__device__ float         g_acc;

// ---------- global union-find ----------
__device__ __forceinline__ int pload(int i) { return __ldcg(&g_parent[i]); }
__device__ __forceinline__ void pstore(int i, int v) { __stcg(&g_parent[i], v); }

__device__ __forceinline__ int uf_find(int i) {
    while (true) {
        int p = pload(i);
        if (p == i) return i;
        int gp = pload(p);
        if (gp == p) return p;
        pstore(i, gp);
        i = gp;
    }
}

__device__ __forceinline__ void uf_union(int a, int b) {
    int ra = uf_find(a);
    int rb = uf_find(b);
    while (ra != rb) {
        if (ra < rb) { int t = ra; ra = rb; rb = t; }
        int old = atomicCAS(&g_parent[ra], ra, rb);
        if (old == ra) return;
        ra = uf_find(old);
        rb = uf_find(rb);
    }
}

// ---------- shared-memory union-find ----------
__device__ __forceinline__ int luf_find(int* sp, int l) {
    volatile int* vp = sp;
    while (true) {
        int p = vp[l];
        if (p == l) return l;
        int gp = vp[p];
        if (gp == p) return p;
        vp[l] = gp;
        l = gp;
    }
}

__device__ __forceinline__ void luf_union(int* sp, int a, int b) {
    int ra = luf_find(sp, a);
    int rb = luf_find(sp, b);
    while (ra != rb) {
        if (ra < rb) { int t = ra; ra = rb; rb = t; }
        int old = atomicCAS(&sp[ra], ra, rb);
        if (old == ra) return;
        ra = luf_find(sp, old);
        rb = luf_find(sp, rb);
    }
}

// ---------------- kernels ----------------

__global__ void k_init(const float* __restrict__ y) {
    int i = blockIdx.x * blockDim.x + threadIdx.x;
    bool f = y[i] > 0.5f;
    unsigned w = __ballot_sync(0xffffffffu, f);
    if ((threadIdx.x & 31) == 0) g_bits[i >> 5] = w;
    g_area[i]  = 0u;
    g_perim[i] = 0u;
    if (i == 0) g_acc = 0.0f;
}

// per-tile union-find in shared memory, write tile-local roots to g_parent
__global__ void __launch_bounds__(1024) k_local() {
    extern __shared__ char smraw[];
    int*      sp    = (int*)smraw;
    unsigned* sbits = (unsigned*)(smraw + TVOX * 4);

    int tid = threadIdx.x;                 // word id in tile, 0..1023
    int wk = tid & 7;                      // x-word in row
    int wy = (tid >> 3) & 15;              // local y
    int wz = tid >> 7;                     // local z
    int ty = blockIdx.x & 15;
    int tz = blockIdx.x >> 4;
    int gy = (ty << 4) + wy;
    int gz = (tz << 3) + wz;
    int gw = (gz << 11) + (gy << 3) + wk;

    unsigned A = g_bits[gw];
    sbits[tid] = A;

    // init local parents with x-run pre-link
    unsigned Alg = (wk > 0) ? g_bits[gw - 1] : 0u;
    unsigned linked = A & ((A << 1) | (Alg >> 31));
    int lbase = tid << 5;
#pragma unroll
    for (int p = 0; p < 32; p++)
        sp[lbase + p] = ((linked >> p) & 1u) ? lbase + p - 1 : lbase + p;
    __syncthreads();

    if (A) {
        unsigned Al = (wk > 0) ? sbits[tid - 1] : 0u;
        unsigned Ar = (wk < 7) ? sbits[tid + 1] : 0u;
        unsigned shlA = (A << 1) | (Al >> 31);
        unsigned shrA = (A >> 1) | (Ar << 31);

        const int dys[4] = { -1, -1, 0, 1 };
        const int dzs[4] = {  0, -1, -1, -1 };
#pragma unroll
        for (int t = 0; t < 4; t++) {
            int ny = wy + dys[t];
            int nz = wz + dzs[t];
            if ((unsigned)ny >= TY || (unsigned)nz >= TZ) continue;   // cross-tile: later
            int nwl = tid + dys[t] * 8 + dzs[t] * 128;
            unsigned B  = sbits[nwl];
            unsigned Bl = (wk > 0) ? sbits[nwl - 1] : 0u;
            unsigned Br = (wk < 7) ? sbits[nwl + 1] : 0u;
            unsigned AB  = A & B;
            unsigned ABl = Al & Bl;
            unsigned shlAB = (AB << 1) | (ABl >> 31);
            unsigned shlB  = (B << 1) | (Bl >> 31);
            unsigned shrB  = (B >> 1) | (Br << 31);

            unsigned Vn  = AB & ~shlAB;
            unsigned DLn = A & ~shlA & shlB & ~B;
            unsigned DRn = A & ~shrA & shrB & ~B;

            int nbase = nwl << 5;
            while (Vn)  { int p = __ffs(Vn)  - 1; Vn  &= Vn  - 1; luf_union(sp, lbase + p, nbase + p); }
            while (DLn) { int p = __ffs(DLn) - 1; DLn &= DLn - 1; luf_union(sp, lbase + p, nbase + p - 1); }
            while (DRn) { int p = __ffs(DRn) - 1; DRn &= DRn - 1; luf_union(sp, lbase + p, nbase + p + 1); }
        }
    }
    __syncthreads();

    // flatten: write global parent = global index of tile-local root (fg only)
    unsigned m = A;
    int gibase = (gz << 16) | (gy << 8) | (wk << 5);
    while (m) {
        int p = __ffs(m) - 1; m &= m - 1;
        int r = luf_find(sp, lbase + p);
        int rx = r & 255, ry = (r >> 8) & 15, rz = (r >> 12) & 7;
        int gr = (((tz << 3) + rz) << 16) | (((ty << 4) + ry) << 8) | rx;
        g_parent[gibase + p] = gr;
    }
}

// global unions only across tile faces (run-pruned)
__global__ void k_xmerge() {
    int w = blockIdx.x * blockDim.x + threadIdx.x;
    unsigned A = g_bits[w];
    if (A == 0u) return;
    int k = w & 7;
    int row = w >> 3;
    int y = row & (HH - 1);
    int z = row >> 8;
    int base = w << 5;

    bool yb0 = (y & 15) == 0;
    bool yb15 = (y & 15) == 15;
    bool zb0 = (z & 7) == 0;
    bool cross[4] = { yb0, yb0 || zb0, zb0, yb15 || zb0 };

    unsigned Al = (k > 0) ? g_bits[w - 1] : 0u;
    unsigned Ar = (k < 7) ? g_bits[w + 1] : 0u;
    unsigned shlA = (A << 1) | (Al >> 31);
    unsigned shrA = (A >> 1) | (Ar << 31);

    const int dys[4] = { -1, -1, 0, 1 };
    const int dzs[4] = {  0, -1, -1, -1 };
#pragma unroll
    for (int t = 0; t < 4; t++) {
        if (!cross[t]) continue;
        int ny = y + dys[t];
        int nz = z + dzs[t];
        if ((unsigned)ny >= HH || (unsigned)nz >= DD) continue;
        int nw = w + dys[t] * 8 + dzs[t] * 2048;
        unsigned B  = g_bits[nw];
        unsigned Bl = (k > 0) ? g_bits[nw - 1] : 0u;
        unsigned Br = (k < 7) ? g_bits[nw + 1] : 0u;
        unsigned AB  = A & B;
        unsigned ABl = Al & Bl;
        unsigned shlAB = (AB << 1) | (ABl >> 31);
        unsigned shlB  = (B << 1) | (Bl >> 31);
        unsigned shrB  = (B >> 1) | (Br << 31);

        unsigned Vn  = AB & ~shlAB;
        unsigned DLn = A & ~shlA & shlB & ~B;
        unsigned DRn = A & ~shrA & shrB & ~B;

        int nbase = nw << 5;
        while (Vn)  { int p = __ffs(Vn)  - 1; Vn  &= Vn  - 1; uf_union(base + p, nbase + p); }
        while (DLn) { int p = __ffs(DLn) - 1; DLn &= DLn - 1; uf_union(base + p, nbase + p - 1); }
        while (DRn) { int p = __ffs(DRn) - 1; DRn &= DRn - 1; uf_union(base + p, nbase + p + 1); }
    }
}

__device__ __forceinline__ void load3(int ry, int rz, int k,
                                      unsigned& c, unsigned& l, unsigned& r) {
    int rw = (rz << 11) + (ry << 3) + k;
    c = g_bits[rw];
    l = (k > 0) ? g_bits[rw - 1] : 0u;
    r = (k < 7) ? g_bits[rw + 1] : 0u;
}

// 18-neighborhood inner boundary, reflect padding
__global__ void k_bnd() {
    int w = blockIdx.x * blockDim.x + threadIdx.x;
    int k = w & 7;
    int row = w >> 3;
    int y = row & (HH - 1);
    int z = row >> 8;
    int ym = (y == 0)      ? 1      : y - 1;
    int yp = (y == HH - 1) ? HH - 2 : y + 1;
    int zm = (z == 0)      ? 1      : z - 1;
    int zp = (z == DD - 1) ? DD - 2 : z + 1;

    unsigned ero = 0xffffffffu;
    unsigned c, l, r;
    load3(y, z, k, c, l, r);
    unsigned shl = (c << 1) | (l >> 31);
    unsigned shr = (c >> 1) | (r << 31);
    if (k == 0) shl |= (c >> 1) & 1u;
    if (k == 7) shr |= ((c >> 30) & 1u) << 31;
    ero &= shl & shr;
    unsigned A = c;

    int eys[4] = { ym, yp, y,  y  };
    int ezs[4] = { z,  z,  zm, zp };
#pragma unroll
    for (int t = 0; t < 4; t++) {
        unsigned cc, ll, rr;
        load3(eys[t], ezs[t], k, cc, ll, rr);
        unsigned s1 = (cc << 1) | (ll >> 31);
        unsigned s2 = (cc >> 1) | (rr << 31);
        if (k == 0) s1 |= (cc >> 1) & 1u;
        if (k == 7) s2 |= ((cc >> 30) & 1u) << 31;
        ero &= cc & s1 & s2;
    }
    int cys[4] = { ym, yp, ym, yp };
    int czs[4] = { zm, zm, zp, zp };
#pragma unroll
    for (int t = 0; t < 4; t++)
        ero &= g_bits[(czs[t] << 11) + (cys[t] << 3) + k];

    g_bnd[w] = A & ~ero;
}

__global__ void k_accum() {
    int i = blockIdx.x * blockDim.x + threadIdx.x;
    unsigned wb = g_bits[i >> 5];
    unsigned bb = g_bnd[i >> 5];
    int lane = i & 31;
    bool f   = (wb >> lane) & 1u;
    bool bnd = (bb >> lane) & 1u;
    int r = -1;
    if (f) r = uf_find(i);
    unsigned peers = __match_any_sync(0xffffffffu, r);
    unsigned bm    = __ballot_sync(0xffffffffu, bnd);
    if (f && (threadIdx.x & 31) == (__ffs(peers) - 1)) {
        atomicAdd(&g_area[r], (unsigned)__popc(peers));
        unsigned pb = (unsigned)__popc(peers & bm);
        if (pb) atomicAdd(&g_perim[r], pb);
    }
}

__global__ void k_reduce() {
    int i = blockIdx.x * blockDim.x + threadIdx.x;
    unsigned wb = g_bits[i >> 5];
    if (((wb >> (i & 31)) & 1u) && __ldcg(&g_parent[i]) == i) {
        float a = (float)g_area[i];
        float p = (float)g_perim[i];
        atomicAdd(&g_acc, FOUR_PI * a / (p * p + EPSF));
    }
}

__global__ void k_final(float* __restrict__ out) {
    float comp = g_acc * (1.0f / (float)DD);
    out[0] = 1.0f / (comp + EPSF);
}

extern "C" void kernel_launch(void* const* d_in, const int* in_sizes, int n_in,
                              void* d_out, int out_size) {
    const float* y = (const float*)d_in[0];
    float* out = (float*)d_out;
    const int threads = 256;

    cudaFuncSetAttribute(k_local, cudaFuncAttributeMaxDynamicSharedMemorySize, SMEM_BYTES);

    k_init<<<NVOX / threads, threads>>>(y);
    k_local<<<128, 1024, SMEM_BYTES>>>();
    k_xmerge<<<NWORD / threads, threads>>>();
    k_bnd<<<NWORD / threads, threads>>>();
    k_accum<<<NVOX / threads, threads>>>();
    k_reduce<<<NVOX / threads, threads>>>();
    k_final<<<1, 1>>>(out);
}

// round 4
// speedup vs baseline: 3.3962x; 1.6717x over previous
#include <cuda_runtime.h>
#include <cuda_bf16.h>
#include <cstdint>

#define DD 64
#define HH 256
#define WW 256
#define NVOX (DD*HH*WW)
#define NWORD (NVOX/32)          // 131072 ; 8 words/row, 2048 words/z-plane
#define EPSF 1e-5f
#define FOUR_PI 12.566370614359172f

// tile = 256(x) x 8(y) x 8(z) = 16384 voxels, 512 words
#define TY 8
#define TZ 8
#define TVOX 16384
#define TWORDS 512
#define NTILES 256               // 32 y-tiles * 8 z-tiles
#define SMEM_BYTES (TVOX*4 + TWORDS*4)   // 66KB

__device__ int           g_parent[NVOX];
__device__ unsigned int  g_area[NVOX];
__device__ unsigned int  g_perim[NVOX];
__device__ unsigned int  g_bits[NWORD];
__device__ unsigned int  g_bnd[NWORD];
__device__ float         g_acc;

// ---------- global union-find ----------
__device__ __forceinline__ int pload(int i) { return __ldcg(&g_parent[i]); }
__device__ __forceinline__ void pstore(int i, int v) { __stcg(&g_parent[i], v); }

__device__ __forceinline__ int uf_find(int i) {
    while (true) {
        int p = pload(i);
        if (p == i) return i;
        int gp = pload(p);
        if (gp == p) return p;
        pstore(i, gp);
        i = gp;
    }
}

__device__ __forceinline__ void uf_union(int a, int b) {
    int ra = uf_find(a);
    int rb = uf_find(b);
    while (ra != rb) {
        if (ra < rb) { int t = ra; ra = rb; rb = t; }
        int old = atomicCAS(&g_parent[ra], ra, rb);
        if (old == ra) return;
        ra = uf_find(old);
        rb = uf_find(rb);
    }
}

// ---------- shared-memory union-find ----------
__device__ __forceinline__ int sread(int* sp, int i) { return ((volatile int*)sp)[i]; }

__device__ __forceinline__ int luf_find(int* sp, int l) {
    volatile int* vp = sp;
    while (true) {
        int p = vp[l];
        if (p == l) return l;
        int gp = vp[p];
        if (gp == p) return p;
        vp[l] = gp;
        l = gp;
    }
}

__device__ __forceinline__ void luf_union(int* sp, int a, int b) {
    int ra = luf_find(sp, a);
    int rb = luf_find(sp, b);
    while (ra != rb) {
        if (ra < rb) { int t = ra; ra = rb; rb = t; }
        int old = atomicCAS(&sp[ra], ra, rb);
        if (old == ra) return;
        ra = luf_find(sp, old);
        rb = luf_find(sp, rb);
    }
}

// ---------------- kernels ----------------

__global__ void k_init(const float* __restrict__ y) {
    int i = blockIdx.x * blockDim.x + threadIdx.x;
    bool f = y[i] > 0.5f;
    unsigned w = __ballot_sync(0xffffffffu, f);
    if ((threadIdx.x & 31) == 0) g_bits[i >> 5] = w;
    g_area[i]  = 0u;
    g_perim[i] = 0u;
    if (i == 0) g_acc = 0.0f;
}

// per-tile union-find in shared memory; write tile roots to g_parent (fg only)
__global__ void __launch_bounds__(TWORDS) k_local() {
    extern __shared__ char smraw[];
    int*      sp    = (int*)smraw;
    unsigned* sbits = (unsigned*)(smraw + TVOX * 4);

    int tid = threadIdx.x;                 // word id in tile, 0..511
    int wk = tid & 7;                      // x-word in row
    int wy = (tid >> 3) & 7;               // local y
    int wz = tid >> 6;                     // local z
    int ty = blockIdx.x & 31;
    int tz = blockIdx.x >> 5;
    int gy = (ty << 3) + wy;
    int gz = (tz << 3) + wz;
    int gw = (gz << 11) + (gy << 3) + wk;

    unsigned A = g_bits[gw];
    sbits[tid] = A;

    // init local parents with x-run pre-link
    unsigned Alg = (wk > 0) ? g_bits[gw - 1] : 0u;
    unsigned linked = A & ((A << 1) | (Alg >> 31));
    int lbase = tid << 5;
#pragma unroll
    for (int p = 0; p < 32; p++)
        sp[lbase + p] = ((linked >> p) & 1u) ? lbase + p - 1 : lbase + p;
    __syncthreads();

    if (A) {
        unsigned Al = (wk > 0) ? sbits[tid - 1] : 0u;
        unsigned Ar = (wk < 7) ? sbits[tid + 1] : 0u;
        unsigned shlA = (A << 1) | (Al >> 31);
        unsigned shrA = (A >> 1) | (Ar << 31);

        int lpa = -1, lpb = -1;    // last-unioned parent pair (dedup cache)

        const int dys[4] = { -1, -1, 0, 1 };
        const int dzs[4] = {  0, -1, -1, -1 };
#pragma unroll
        for (int t = 0; t < 4; t++) {
            int ny = wy + dys[t];
            int nz = wz + dzs[t];
            if ((unsigned)ny >= TY || (unsigned)nz >= TZ) continue;   // cross-tile later
            int nwl = tid + dys[t] * 8 + dzs[t] * 64;
            unsigned B  = sbits[nwl];
            unsigned Bl = (wk > 0) ? sbits[nwl - 1] : 0u;
            unsigned Br = (wk < 7) ? sbits[nwl + 1] : 0u;
            unsigned AB  = A & B;
            unsigned ABl = Al & Bl;
            unsigned shlAB = (AB << 1) | (ABl >> 31);
            unsigned shlB  = (B << 1) | (Bl >> 31);
            unsigned shrB  = (B >> 1) | (Br << 31);

            unsigned Vn  = AB & ~shlAB;
            unsigned DLn = A & ~shlA & shlB & ~B;
            unsigned DRn = A & ~shrA & shrB & ~B;

            int nbase = nwl << 5;
#define LEDGE(aa, bb)                                                     \
            { int pa = sread(sp, aa), pb = sread(sp, bb);                 \
              if (pa != lpa || pb != lpb) { lpa = pa; lpb = pb;           \
                  luf_union(sp, pa, pb); } }
            while (Vn)  { int p = __ffs(Vn)  - 1; Vn  &= Vn  - 1; LEDGE(lbase + p, nbase + p); }
            while (DLn) { int p = __ffs(DLn) - 1; DLn &= DLn - 1; LEDGE(lbase + p, nbase + p - 1); }
            while (DRn) { int p = __ffs(DRn) - 1; DRn &= DRn - 1; LEDGE(lbase + p, nbase + p + 1); }
#undef LEDGE
        }
    }
    __syncthreads();

    // flatten: g_parent[voxel] = global index of tile-local root (fg only)
    unsigned m = A;
    int gibase = (gz << 16) | (gy << 8) | (wk << 5);
    while (m) {
        int p = __ffs(m) - 1; m &= m - 1;
        int r = luf_find(sp, lbase + p);
        int rx = r & 255, ry = (r >> 8) & 7, rz = r >> 11;
        int gr = (((tz << 3) + rz) << 16) | (((ty << 3) + ry) << 8) | rx;
        g_parent[gibase + p] = gr;
    }
}

// global unions only across tile faces (run-pruned + pair-dedup)
__global__ void k_xmerge() {
    int w = blockIdx.x * blockDim.x + threadIdx.x;
    unsigned A = g_bits[w];
    if (A == 0u) return;
    int k = w & 7;
    int row = w >> 3;
    int y = row & (HH - 1);
    int z = row >> 8;
    int base = w << 5;

    bool yb0 = (y & 7) == 0;
    bool yb7 = (y & 7) == 7;
    bool zb0 = (z & 7) == 0;
    bool cross[4] = { yb0, yb0 || zb0, zb0, yb7 || zb0 };
    if (!(cross[0] | cross[1] | cross[2] | cross[3])) return;

    unsigned Al = (k > 0) ? g_bits[w - 1] : 0u;
    unsigned Ar = (k < 7) ? g_bits[w + 1] : 0u;
    unsigned shlA = (A << 1) | (Al >> 31);
    unsigned shrA = (A >> 1) | (Ar << 31);

    int lpa = -1, lpb = -1;

    const int dys[4] = { -1, -1, 0, 1 };
    const int dzs[4] = {  0, -1, -1, -1 };
#pragma unroll
    for (int t = 0; t < 4; t++) {
        if (!cross[t]) continue;
        int ny = y + dys[t];
        int nz = z + dzs[t];
        if ((unsigned)ny >= HH || (unsigned)nz >= DD) continue;
        int nw = w + dys[t] * 8 + dzs[t] * 2048;
        unsigned B  = g_bits[nw];
        unsigned Bl = (k > 0) ? g_bits[nw - 1] : 0u;
        unsigned Br = (k < 7) ? g_bits[nw + 1] : 0u;
        unsigned AB  = A & B;
        unsigned ABl = Al & Bl;
        unsigned shlAB = (AB << 1) | (ABl >> 31);
        unsigned shlB  = (B << 1) | (Bl >> 31);
        unsigned shrB  = (B >> 1) | (Br << 31);

        unsigned Vn  = AB & ~shlAB;
        unsigned DLn = A & ~shlA & shlB & ~B;
        unsigned DRn = A & ~shrA & shrB & ~B;

        int nbase = nw << 5;
#define GEDGE(aa, bb)                                                     \
        { int pa = pload(aa), pb = pload(bb);                             \
          if (pa != lpa || pb != lpb) { lpa = pa; lpb = pb;               \
              uf_union(pa, pb); } }
        while (Vn)  { int p = __ffs(Vn)  - 1; Vn  &= Vn  - 1; GEDGE(base + p, nbase + p); }
        while (DLn) { int p = __ffs(DLn) - 1; DLn &= DLn - 1; GEDGE(base + p, nbase + p - 1); }
        while (DRn) { int p = __ffs(DRn) - 1; DRn &= DRn - 1; GEDGE(base + p, nbase + p + 1); }
#undef GEDGE
    }
}

__device__ __forceinline__ void load3(int ry, int rz, int k,
                                      unsigned& c, unsigned& l, unsigned& r) {
    int rw = (rz << 11) + (ry << 3) + k;
    c = g_bits[rw];
    l = (k > 0) ? g_bits[rw - 1] : 0u;
    r = (k < 7) ? g_bits[rw + 1] : 0u;
}

// 18-neighborhood inner boundary, reflect padding
__global__ void k_bnd() {
    int w = blockIdx.x * blockDim.x + threadIdx.x;
    int k = w & 7;
    int row = w >> 3;
    int y = row & (HH - 1);
    int z = row >> 8;
    int ym = (y == 0)      ? 1      : y - 1;
    int yp = (y == HH - 1) ? HH - 2 : y + 1;
    int zm = (z == 0)      ? 1      : z - 1;
    int zp = (z == DD - 1) ? DD - 2 : z + 1;

    unsigned ero = 0xffffffffu;
    unsigned c, l, r;
    load3(y, z, k, c, l, r);
    unsigned shl = (c << 1) | (l >> 31);
    unsigned shr = (c >> 1) | (r << 31);
    if (k == 0) shl |= (c >> 1) & 1u;
    if (k == 7) shr |= ((c >> 30) & 1u) << 31;
    ero &= shl & shr;
    unsigned A = c;

    int eys[4] = { ym, yp, y,  y  };
    int ezs[4] = { z,  z,  zm, zp };
#pragma unroll
    for (int t = 0; t < 4; t++) {
        unsigned cc, ll, rr;
        load3(eys[t], ezs[t], k, cc, ll, rr);
        unsigned s1 = (cc << 1) | (ll >> 31);
        unsigned s2 = (cc >> 1) | (rr << 31);
        if (k == 0) s1 |= (cc >> 1) & 1u;
        if (k == 7) s2 |= ((cc >> 30) & 1u) << 31;
        ero &= cc & s1 & s2;
    }
    int cys[4] = { ym, yp, ym, yp };
    int czs[4] = { zm, zm, zp, zp };
#pragma unroll
    for (int t = 0; t < 4; t++)
        ero &= g_bits[(czs[t] << 11) + (cys[t] << 3) + k];

    g_bnd[w] = A & ~ero;
}

__global__ void k_accum() {
    int i = blockIdx.x * blockDim.x + threadIdx.x;
    unsigned wb = g_bits[i >> 5];
    unsigned bb = g_bnd[i >> 5];
    int lane = i & 31;
    bool f   = (wb >> lane) & 1u;
    bool bnd = (bb >> lane) & 1u;
    int r = -1;
    if (f) r = uf_find(i);
    unsigned peers = __match_any_sync(0xffffffffu, r);
    unsigned bm    = __ballot_sync(0xffffffffu, bnd);
    if (f && (threadIdx.x & 31) == (__ffs(peers) - 1)) {
        atomicAdd(&g_area[r], (unsigned)__popc(peers));
        unsigned pb = (unsigned)__popc(peers & bm);
        if (pb) atomicAdd(&g_perim[r], pb);
    }
}

__global__ void k_reduce() {
    int i = blockIdx.x * blockDim.x + threadIdx.x;
    unsigned wb = g_bits[i >> 5];
    if (((wb >> (i & 31)) & 1u) && __ldcg(&g_parent[i]) == i) {
        float a = (float)g_area[i];
        float p = (float)g_perim[i];
        atomicAdd(&g_acc, FOUR_PI * a / (p * p + EPSF));
    }
}

__global__ void k_final(float* __restrict__ out) {
    float comp = g_acc * (1.0f / (float)DD);
    out[0] = 1.0f / (comp + EPSF);
}

extern "C" void kernel_launch(void* const* d_in, const int* in_sizes, int n_in,
                              void* d_out, int out_size) {
    const float* y = (const float*)d_in[0];
    float* out = (float*)d_out;
    const int threads = 256;

    cudaFuncSetAttribute(k_local, cudaFuncAttributeMaxDynamicSharedMemorySize, SMEM_BYTES);

    k_init<<<NVOX / threads, threads>>>(y);
    k_local<<<NTILES, TWORDS, SMEM_BYTES>>>();
    k_xmerge<<<NWORD / threads, threads>>>();
    k_bnd<<<NWORD / threads, threads>>>();
    k_accum<<<NVOX / threads, threads>>>();
    k_reduce<<<NVOX / threads, threads>>>();
    k_final<<<1, 1>>>(out);
}

// round 5
// speedup vs baseline: 4.6714x; 1.3755x over previous
#include <cuda_runtime.h>
#include <cuda_bf16.h>
#include <cstdint>

#define DD 64
#define HH 256
#define WW 256
#define NVOX (DD*HH*WW)
#define NWORD (NVOX/32)          // 131072 ; 8 words/row, 2048 words/z-plane
#define EPSF 1e-5f
#define FOUR_PI 12.566370614359172f

// tile = 256(x) x 8(y) x 8(z) = 16384 voxels, 512 words
#define TY 8
#define TZ 8
#define TVOX 16384
#define TWORDS 512
#define NTILES 256               // 32 y-tiles * 8 z-tiles
#define SMEM_BYTES (TVOX*4 + TWORDS*4)   // 66KB

__device__ int           g_parent[NVOX];
__device__ unsigned int  g_area[NVOX];    // zero-invariant: only dirtied entries re-zeroed
__device__ unsigned int  g_perim[NVOX];
__device__ unsigned int  g_bits[NWORD];
__device__ unsigned int  g_bnd[NWORD];
__device__ float         g_acc;

// ---------- global union-find ----------
__device__ __forceinline__ int pload(int i) { return __ldcg(&g_parent[i]); }
__device__ __forceinline__ void pstore(int i, int v) { __stcg(&g_parent[i], v); }

__device__ __forceinline__ int uf_find(int i) {
    while (true) {
        int p = pload(i);
        if (p == i) return i;
        int gp = pload(p);
        if (gp == p) return p;
        pstore(i, gp);
        i = gp;
    }
}

__device__ __forceinline__ void uf_union(int a, int b) {
    int ra = uf_find(a);
    int rb = uf_find(b);
    while (ra != rb) {
        if (ra < rb) { int t = ra; ra = rb; rb = t; }
        int old = atomicCAS(&g_parent[ra], ra, rb);
        if (old == ra) return;
        ra = uf_find(old);
        rb = uf_find(rb);
    }
}

// ---------- shared-memory union-find ----------
__device__ __forceinline__ int sread(int* sp, int i) { return ((volatile int*)sp)[i]; }

__device__ __forceinline__ int luf_find(int* sp, int l) {
    volatile int* vp = sp;
    while (true) {
        int p = vp[l];
        if (p == l) return l;
        int gp = vp[p];
        if (gp == p) return p;
        vp[l] = gp;
        l = gp;
    }
}

__device__ __forceinline__ void luf_union(int* sp, int a, int b) {
    int ra = luf_find(sp, a);
    int rb = luf_find(sp, b);
    while (ra != rb) {
        if (ra < rb) { int t = ra; ra = rb; rb = t; }
        int old = atomicCAS(&sp[ra], ra, rb);
        if (old == ra) return;
        ra = luf_find(sp, old);
        rb = luf_find(sp, rb);
    }
}

// ---------------- kernels ----------------

// 4 voxels/thread, float4 loads, shfl-packed bit words; no big clears
__global__ void k_init(const float4* __restrict__ y4) {
    int t = blockIdx.x * blockDim.x + threadIdx.x;      // NVOX/4 threads
    float4 v = y4[t];
    unsigned nib = (unsigned)(v.x > 0.5f)
                 | ((unsigned)(v.y > 0.5f) << 1)
                 | ((unsigned)(v.z > 0.5f) << 2)
                 | ((unsigned)(v.w > 0.5f) << 3);
    unsigned val = nib << (4 * (threadIdx.x & 7));
#pragma unroll
    for (int d = 1; d < 8; d <<= 1)
        val |= __shfl_xor_sync(0xffffffffu, val, d);
    if ((threadIdx.x & 7) == 0) g_bits[t >> 3] = val;
    if (t == 0) g_acc = 0.0f;
}

// per-tile union-find in shared memory; 2 threads per word (split directions)
__global__ void __launch_bounds__(1024) k_local() {
    extern __shared__ char smraw[];
    int*      sp    = (int*)smraw;
    unsigned* sbits = (unsigned*)(smraw + TVOX * 4);

    int tid  = threadIdx.x;
    int wid2 = tid >> 1;                   // word 0..511
    int half = tid & 1;
    int wk = wid2 & 7;
    int wy = (wid2 >> 3) & 7;
    int wz = wid2 >> 6;
    int ty = blockIdx.x & 31;
    int tz = blockIdx.x >> 5;
    int gy = (ty << 3) + wy;
    int gz = (tz << 3) + wz;
    int gw = (gz << 11) + (gy << 3) + wk;

    unsigned A = g_bits[gw];
    if (half == 0) sbits[wid2] = A;

    // x-run pre-link; each half-thread inits 16 parents
    unsigned Alg = (wk > 0) ? g_bits[gw - 1] : 0u;
    unsigned linked = A & ((A << 1) | (Alg >> 31));
    int lbase = wid2 << 5;
    int pstart = half << 4;
#pragma unroll
    for (int p = 0; p < 16; p++) {
        int q = pstart + p;
        sp[lbase + q] = ((linked >> q) & 1u) ? lbase + q - 1 : lbase + q;
    }
    __syncthreads();

    if (A) {
        unsigned Al = (wk > 0) ? sbits[wid2 - 1] : 0u;
        unsigned Ar = (wk < 7) ? sbits[wid2 + 1] : 0u;
        unsigned shlA = (A << 1) | (Al >> 31);
        unsigned shrA = (A >> 1) | (Ar << 31);

        int lpa = -1, lpb = -1;    // pair-dedup cache

        const int dys[4] = { -1, -1, 0, 1 };
        const int dzs[4] = {  0, -1, -1, -1 };
        for (int t = half; t < 4; t += 2) {     // 2 directions per thread
            int ny = wy + dys[t];
            int nz = wz + dzs[t];
            if ((unsigned)ny >= TY || (unsigned)nz >= TZ) continue;   // cross-tile later
            int nwl = wid2 + dys[t] * 8 + dzs[t] * 64;
            unsigned B  = sbits[nwl];
            unsigned Bl = (wk > 0) ? sbits[nwl - 1] : 0u;
            unsigned Br = (wk < 7) ? sbits[nwl + 1] : 0u;
            unsigned AB  = A & B;
            unsigned ABl = Al & Bl;
            unsigned shlAB = (AB << 1) | (ABl >> 31);
            unsigned shlB  = (B << 1) | (Bl >> 31);
            unsigned shrB  = (B >> 1) | (Br << 31);

            unsigned Vn  = AB & ~shlAB;
            unsigned DLn = A & ~shlA & shlB & ~B;
            unsigned DRn = A & ~shrA & shrB & ~B;

            int nbase = nwl << 5;
#define LEDGE(aa, bb)                                                     \
            { int pa = sread(sp, aa), pb = sread(sp, bb);                 \
              if (pa != lpa || pb != lpb) { lpa = pa; lpb = pb;           \
                  luf_union(sp, pa, pb); } }
            while (Vn)  { int p = __ffs(Vn)  - 1; Vn  &= Vn  - 1; LEDGE(lbase + p, nbase + p); }
            while (DLn) { int p = __ffs(DLn) - 1; DLn &= DLn - 1; LEDGE(lbase + p, nbase + p - 1); }
            while (DRn) { int p = __ffs(DRn) - 1; DRn &= DRn - 1; LEDGE(lbase + p, nbase + p + 1); }
#undef LEDGE
        }
    }
    __syncthreads();

    // flatten: g_parent[voxel] = global index of tile-local root; 16 bits/thread
    unsigned m = A & (half ? 0xFFFF0000u : 0x0000FFFFu);
    int gibase = (gz << 16) | (gy << 8) | (wk << 5);
    while (m) {
        int p = __ffs(m) - 1; m &= m - 1;
        int r = luf_find(sp, lbase + p);
        int rx = r & 255, ry = (r >> 8) & 7, rz = r >> 11;
        int gr = (((tz << 3) + rz) << 16) | (((ty << 3) + ry) << 8) | rx;
        g_parent[gibase + p] = gr;
    }
}

// global unions only across tile faces (run-pruned + pair-dedup)
__global__ void k_xmerge() {
    int w = blockIdx.x * blockDim.x + threadIdx.x;
    unsigned A = g_bits[w];
    if (A == 0u) return;
    int k = w & 7;
    int row = w >> 3;
    int y = row & (HH - 1);
    int z = row >> 8;
    int base = w << 5;

    bool yb0 = (y & 7) == 0;
    bool yb7 = (y & 7) == 7;
    bool zb0 = (z & 7) == 0;
    bool cross[4] = { yb0, yb0 || zb0, zb0, yb7 || zb0 };
    if (!(cross[0] | cross[1] | cross[2] | cross[3])) return;

    unsigned Al = (k > 0) ? g_bits[w - 1] : 0u;
    unsigned Ar = (k < 7) ? g_bits[w + 1] : 0u;
    unsigned shlA = (A << 1) | (Al >> 31);
    unsigned shrA = (A >> 1) | (Ar << 31);

    int lpa = -1, lpb = -1;

    const int dys[4] = { -1, -1, 0, 1 };
    const int dzs[4] = {  0, -1, -1, -1 };
#pragma unroll
    for (int t = 0; t < 4; t++) {
        if (!cross[t]) continue;
        int ny = y + dys[t];
        int nz = z + dzs[t];
        if ((unsigned)ny >= HH || (unsigned)nz >= DD) continue;
        int nw = w + dys[t] * 8 + dzs[t] * 2048;
        unsigned B  = g_bits[nw];
        unsigned Bl = (k > 0) ? g_bits[nw - 1] : 0u;
        unsigned Br = (k < 7) ? g_bits[nw + 1] : 0u;
        unsigned AB  = A & B;
        unsigned ABl = Al & Bl;
        unsigned shlAB = (AB << 1) | (ABl >> 31);
        unsigned shlB  = (B << 1) | (Bl >> 31);
        unsigned shrB  = (B >> 1) | (Br << 31);

        unsigned Vn  = AB & ~shlAB;
        unsigned DLn = A & ~shlA & shlB & ~B;
        unsigned DRn = A & ~shrA & shrB & ~B;

        int nbase = nw << 5;
#define GEDGE(aa, bb)                                                     \
        { int pa = pload(aa), pb = pload(bb);                             \
          if (pa != lpa || pb != lpb) { lpa = pa; lpb = pb;               \
              uf_union(pa, pb); } }
        while (Vn)  { int p = __ffs(Vn)  - 1; Vn  &= Vn  - 1; GEDGE(base + p, nbase + p); }
        while (DLn) { int p = __ffs(DLn) - 1; DLn &= DLn - 1; GEDGE(base + p, nbase + p - 1); }
        while (DRn) { int p = __ffs(DRn) - 1; DRn &= DRn - 1; GEDGE(base + p, nbase + p + 1); }
#undef GEDGE
    }
}

__device__ __forceinline__ void load3(int ry, int rz, int k,
                                      unsigned& c, unsigned& l, unsigned& r) {
    int rw = (rz << 11) + (ry << 3) + k;
    c = g_bits[rw];
    l = (k > 0) ? g_bits[rw - 1] : 0u;
    r = (k < 7) ? g_bits[rw + 1] : 0u;
}

// 18-neighborhood inner boundary, reflect padding
__global__ void k_bnd() {
    int w = blockIdx.x * blockDim.x + threadIdx.x;
    int k = w & 7;
    int row = w >> 3;
    int y = row & (HH - 1);
    int z = row >> 8;
    int ym = (y == 0)      ? 1      : y - 1;
    int yp = (y == HH - 1) ? HH - 2 : y + 1;
    int zm = (z == 0)      ? 1      : z - 1;
    int zp = (z == DD - 1) ? DD - 2 : z + 1;

    unsigned ero = 0xffffffffu;
    unsigned c, l, r;
    load3(y, z, k, c, l, r);
    unsigned shl = (c << 1) | (l >> 31);
    unsigned shr = (c >> 1) | (r << 31);
    if (k == 0) shl |= (c >> 1) & 1u;
    if (k == 7) shr |= ((c >> 30) & 1u) << 31;
    ero &= shl & shr;
    unsigned A = c;

    int eys[4] = { ym, yp, y,  y  };
    int ezs[4] = { z,  z,  zm, zp };
#pragma unroll
    for (int t = 0; t < 4; t++) {
        unsigned cc, ll, rr;
        load3(eys[t], ezs[t], k, cc, ll, rr);
        unsigned s1 = (cc << 1) | (ll >> 31);
        unsigned s2 = (cc >> 1) | (rr << 31);
        if (k == 0) s1 |= (cc >> 1) & 1u;
        if (k == 7) s2 |= ((cc >> 30) & 1u) << 31;
        ero &= cc & s1 & s2;
    }
    int cys[4] = { ym, yp, ym, yp };
    int czs[4] = { zm, zm, zp, zp };
#pragma unroll
    for (int t = 0; t < 4; t++)
        ero &= g_bits[(czs[t] << 11) + (cys[t] << 3) + k];

    g_bnd[w] = A & ~ero;
}

// accumulate onto parent pointer (tile root) directly — NO find chain
__global__ void k_accum() {
    int i = blockIdx.x * blockDim.x + threadIdx.x;
    unsigned wb = g_bits[i >> 5];
    unsigned bb = g_bnd[i >> 5];
    int lane = i & 31;
    bool f   = (wb >> lane) & 1u;
    bool bnd = (bb >> lane) & 1u;
    int r = -1;
    if (f) r = pload(i);
    unsigned peers = __match_any_sync(0xffffffffu, r);
    unsigned bm    = __ballot_sync(0xffffffffu, bnd);
    if (f && (threadIdx.x & 31) == (__ffs(peers) - 1)) {
        atomicAdd(&g_area[r], (unsigned)__popc(peers));
        unsigned pb = (unsigned)__popc(peers & bm);
        if (pb) atomicAdd(&g_perim[r], pb);
    }
}

// forward counts from non-root dirtied nodes to final roots; re-zero sources
__global__ void k_push() {
    int i = blockIdx.x * blockDim.x + threadIdx.x;
    unsigned wb = g_bits[i >> 5];
    if (!((wb >> (i & 31)) & 1u)) return;
    unsigned a = g_area[i];
    if (a == 0u) return;
    if (pload(i) == i) return;            // true root keeps its counts
    int r = uf_find(i);
    unsigned pm = g_perim[i];
    atomicAdd(&g_area[r], a);
    g_area[i] = 0u;
    if (pm) { atomicAdd(&g_perim[r], pm); g_perim[i] = 0u; }
}

// roots: contribution + restore zero-invariant
__global__ void k_reduce() {
    int i = blockIdx.x * blockDim.x + threadIdx.x;
    unsigned wb = g_bits[i >> 5];
    if (!((wb >> (i & 31)) & 1u)) return;
    if (pload(i) != i) return;
    float a = (float)g_area[i];
    float p = (float)g_perim[i];
    g_area[i]  = 0u;
    g_perim[i] = 0u;
    atomicAdd(&g_acc, FOUR_PI * a / (p * p + EPSF));
}

__global__ void k_final(float* __restrict__ out) {
    float comp = g_acc * (1.0f / (float)DD);
    out[0] = 1.0f / (comp + EPSF);
}

extern "C" void kernel_launch(void* const* d_in, const int* in_sizes, int n_in,
                              void* d_out, int out_size) {
    const float4* y4 = (const float4*)d_in[0];
    float* out = (float*)d_out;
    const int threads = 256;

    cudaFuncSetAttribute(k_local, cudaFuncAttributeMaxDynamicSharedMemorySize, SMEM_BYTES);

    k_init<<<(NVOX / 4) / threads, threads>>>(y4);
    k_local<<<NTILES, 1024, SMEM_BYTES>>>();
    k_xmerge<<<NWORD / threads, threads>>>();
    k_bnd<<<NWORD / threads, threads>>>();
    k_accum<<<NVOX / threads, threads>>>();
    k_push<<<NVOX / threads, threads>>>();
    k_reduce<<<NVOX / threads, threads>>>();
    k_final<<<1, 1>>>(out);
}

// round 6
// speedup vs baseline: 4.9981x; 1.0699x over previous
#include <cuda_runtime.h>
#include <cuda_bf16.h>
#include <cstdint>

#define DD 64
#define HH 256
#define WW 256
#define NVOX (DD*HH*WW)
#define NWORD (NVOX/32)          // 131072 ; 8 words/row, 2048 words/z-plane
#define EPSF 1e-5f
#define FOUR_PI 12.566370614359172f

// tile = 256(x) x 8(y) x 8(z) = 16384 voxels, 512 words
#define TY 8
#define TZ 8
#define TVOX 16384
#define TWORDS 512
#define NTILES 256               // 32 y-tiles * 8 z-tiles
#define SMEM_BYTES (TVOX*4 + TWORDS*4 + TWORDS*4)   // parents + bits + bnd = 68KB
#define MAXROOTS 600000

__device__ int           g_parent[NVOX];
__device__ unsigned int  g_area[NVOX];    // only tile-root entries meaningful (stored fresh each run)
__device__ unsigned int  g_perim[NVOX];
__device__ unsigned int  g_bits[NWORD];
__device__ int           g_roots[MAXROOTS];
__device__ int           g_nroots;
__device__ float         g_acc;

// ---------- global union-find ----------
__device__ __forceinline__ int pload(int i) { return __ldcg(&g_parent[i]); }
__device__ __forceinline__ void pstore(int i, int v) { __stcg(&g_parent[i], v); }

__device__ __forceinline__ int uf_find(int i) {
    while (true) {
        int p = pload(i);
        if (p == i) return i;
        int gp = pload(p);
        if (gp == p) return p;
        pstore(i, gp);
        i = gp;
    }
}

__device__ __forceinline__ void uf_union(int a, int b) {
    int ra = uf_find(a);
    int rb = uf_find(b);
    while (ra != rb) {
        if (ra < rb) { int t = ra; ra = rb; rb = t; }
        int old = atomicCAS(&g_parent[ra], ra, rb);
        if (old == ra) return;
        ra = uf_find(old);
        rb = uf_find(rb);
    }
}

// ---------- shared-memory union-find ----------
__device__ __forceinline__ int sread(int* sp, int i) { return ((volatile int*)sp)[i]; }

__device__ __forceinline__ int luf_find(int* sp, int l) {
    volatile int* vp = sp;
    while (true) {
        int p = vp[l];
        if (p == l) return l;
        int gp = vp[p];
        if (gp == p) return p;
        vp[l] = gp;
        l = gp;
    }
}

__device__ __forceinline__ void luf_union(int* sp, int a, int b) {
    int ra = luf_find(sp, a);
    int rb = luf_find(sp, b);
    while (ra != rb) {
        if (ra < rb) { int t = ra; ra = rb; rb = t; }
        int old = atomicCAS(&sp[ra], ra, rb);
        if (old == ra) return;
        ra = luf_find(sp, old);
        rb = luf_find(sp, rb);
    }
}

// ---------------- kernels ----------------

// 4 voxels/thread, float4 loads, shfl-packed bit words
__global__ void k_init(const float4* __restrict__ y4) {
    int t = blockIdx.x * blockDim.x + threadIdx.x;      // NVOX/4 threads
    float4 v = y4[t];
    unsigned nib = (unsigned)(v.x > 0.5f)
                 | ((unsigned)(v.y > 0.5f) << 1)
                 | ((unsigned)(v.z > 0.5f) << 2)
                 | ((unsigned)(v.w > 0.5f) << 3);
    unsigned val = nib << (4 * (threadIdx.x & 7));
#pragma unroll
    for (int d = 1; d < 8; d <<= 1)
        val |= __shfl_xor_sync(0xffffffffu, val, d);
    if ((threadIdx.x & 7) == 0) g_bits[t >> 3] = val;
    if (t == 0) { g_acc = 0.0f; g_nroots = 0; }
}

// fused: per-tile UF + inline 18-conn boundary + per-root counting
__global__ void __launch_bounds__(1024) k_local() {
    extern __shared__ char smraw[];
    int*      sp    = (int*)smraw;
    unsigned* sbits = (unsigned*)(smraw + TVOX * 4);
    unsigned* sbnd  = (unsigned*)(smraw + TVOX * 4 + TWORDS * 4);

    int tid  = threadIdx.x;
    int wid2 = tid >> 1;                   // word 0..511
    int half = tid & 1;
    int wk = wid2 & 7;
    int wy = (wid2 >> 3) & 7;
    int wz = wid2 >> 6;
    int ty = blockIdx.x & 31;
    int tz = blockIdx.x >> 5;
    int gy = (ty << 3) + wy;
    int gz = (tz << 3) + wz;
    int gw = (gz << 11) + (gy << 3) + wk;
    int lbase = wid2 << 5;

    unsigned A = g_bits[gw];

    if (half == 1) {
        sbits[wid2] = A;
        // x-run pre-link for all 32 bits of the word
        unsigned Alg = (wk > 0) ? g_bits[gw - 1] : 0u;
        unsigned linked = A & ((A << 1) | (Alg >> 31));
#pragma unroll
        for (int p = 0; p < 32; p++)
            sp[lbase + p] = ((linked >> p) & 1u) ? lbase + p - 1 : lbase + p;
    } else {
        // inline boundary (18-neigh erosion, reflect padding) -> sbnd
        unsigned bw = 0u;
        if (A) {
            int ym = (gy == 0)      ? 1      : gy - 1;
            int yp = (gy == HH - 1) ? HH - 2 : gy + 1;
            int zm = (gz == 0)      ? 1      : gz - 1;
            int zp = (gz == DD - 1) ? DD - 2 : gz + 1;
            unsigned ero = 0xffffffffu;
            {
                unsigned l = (wk > 0) ? g_bits[gw - 1] : 0u;
                unsigned r = (wk < 7) ? g_bits[gw + 1] : 0u;
                unsigned shl = (A << 1) | (l >> 31);
                unsigned shr = (A >> 1) | (r << 31);
                if (wk == 0) shl |= (A >> 1) & 1u;
                if (wk == 7) shr |= ((A >> 30) & 1u) << 31;
                ero &= shl & shr;
            }
            int eys[4] = { ym, yp, gy, gy };
            int ezs[4] = { gz, gz, zm, zp };
#pragma unroll
            for (int t = 0; t < 4; t++) {
                int rw = (ezs[t] << 11) + (eys[t] << 3) + wk;
                unsigned cc = g_bits[rw];
                unsigned ll = (wk > 0) ? g_bits[rw - 1] : 0u;
                unsigned rr = (wk < 7) ? g_bits[rw + 1] : 0u;
                unsigned s1 = (cc << 1) | (ll >> 31);
                unsigned s2 = (cc >> 1) | (rr << 31);
                if (wk == 0) s1 |= (cc >> 1) & 1u;
                if (wk == 7) s2 |= ((cc >> 30) & 1u) << 31;
                ero &= cc & s1 & s2;
            }
            int cys[4] = { ym, yp, ym, yp };
            int czs[4] = { zm, zm, zp, zp };
#pragma unroll
            for (int t = 0; t < 4; t++)
                ero &= g_bits[(czs[t] << 11) + (cys[t] << 3) + wk];
            bw = A & ~ero;
        }
        sbnd[wid2] = bw;
    }
    __syncthreads();

    // union phase: 2 directions per thread, run-pruned + pair-dedup
    if (A) {
        unsigned Al = (wk > 0) ? sbits[wid2 - 1] : 0u;
        unsigned Ar = (wk < 7) ? sbits[wid2 + 1] : 0u;
        unsigned shlA = (A << 1) | (Al >> 31);
        unsigned shrA = (A >> 1) | (Ar << 31);

        int lpa = -1, lpb = -1;

        const int dys[4] = { -1, -1, 0, 1 };
        const int dzs[4] = {  0, -1, -1, -1 };
        for (int t = half; t < 4; t += 2) {
            int ny = wy + dys[t];
            int nz = wz + dzs[t];
            if ((unsigned)ny >= TY || (unsigned)nz >= TZ) continue;
            int nwl = wid2 + dys[t] * 8 + dzs[t] * 64;
            unsigned B  = sbits[nwl];
            unsigned Bl = (wk > 0) ? sbits[nwl - 1] : 0u;
            unsigned Br = (wk < 7) ? sbits[nwl + 1] : 0u;
            unsigned AB  = A & B;
            unsigned ABl = Al & Bl;
            unsigned shlAB = (AB << 1) | (ABl >> 31);
            unsigned shlB  = (B << 1) | (Bl >> 31);
            unsigned shrB  = (B >> 1) | (Br << 31);

            unsigned Vn  = AB & ~shlAB;
            unsigned DLn = A & ~shlA & shlB & ~B;
            unsigned DRn = A & ~shrA & shrB & ~B;

            int nbase = nwl << 5;
#define LEDGE(aa, bb)                                                     \
            { int pa = sread(sp, aa), pb = sread(sp, bb);                 \
              if (pa != lpa || pb != lpb) { lpa = pa; lpb = pb;           \
                  luf_union(sp, pa, pb); } }
            while (Vn)  { int p = __ffs(Vn)  - 1; Vn  &= Vn  - 1; LEDGE(lbase + p, nbase + p); }
            while (DLn) { int p = __ffs(DLn) - 1; DLn &= DLn - 1; LEDGE(lbase + p, nbase + p - 1); }
            while (DRn) { int p = __ffs(DRn) - 1; DRn &= DRn - 1; LEDGE(lbase + p, nbase + p + 1); }
#undef LEDGE
        }
    }
    __syncthreads();

    // phase 1: full compression + face/root global parent writes + root list
    unsigned mymask = half ? 0xFFFF0000u : 0x0000FFFFu;
    unsigned m = A & mymask;
    unsigned rootmask = 0u;
    int gibase = (gz << 16) | (gy << 8) | (wk << 5);
    bool isface = (wy == 0) | (wy == TY - 1) | (wz == 0) | (wz == TZ - 1);
    while (m) {
        int p = __ffs(m) - 1; m &= m - 1;
        int v = lbase + p;
        int r = luf_find(sp, v);
        sp[v] = r;                          // full compression
        if (r == v) {
            rootmask |= 1u << p;
            g_parent[gibase + p] = gibase + p;
            int slot = atomicAdd(&g_nroots, 1);
            g_roots[slot] = gibase + p;
        } else if (isface) {
            int rx = r & 255, ry = (r >> 8) & 7, rz = r >> 11;
            g_parent[gibase + p] =
                (((tz << 3) + rz) << 16) | (((ty << 3) + ry) << 8) | rx;
        }
    }
    __syncthreads();

    // phase 2: zero root counters (repurpose sp entries at root indices)
    unsigned mr = rootmask;
    while (mr) { int p = __ffs(mr) - 1; mr &= mr - 1; sp[lbase + p] = 0; }
    __syncthreads();

    // phase 3: accumulate packed (perim<<16 | area) with per-thread run aggregation
    m = A & mymask;
    if (m) {
        unsigned bw = sbnd[wid2];
        int curr = -1; unsigned accv = 0u;
        while (m) {
            int p = __ffs(m) - 1; m &= m - 1;
            int v = lbase + p;
            int r = ((rootmask >> p) & 1u) ? v : sp[v];
            unsigned add = 1u + (((bw >> p) & 1u) << 16);
            if (r == curr) accv += add;
            else {
                if (curr >= 0) atomicAdd((unsigned*)&sp[curr], accv);
                curr = r; accv = add;
            }
        }
        atomicAdd((unsigned*)&sp[curr], accv);
    }
    __syncthreads();

    // phase 4: root owners publish counts (exclusive -> plain stores)
    mr = rootmask;
    while (mr) {
        int p = __ffs(mr) - 1; mr &= mr - 1;
        unsigned cv = (unsigned)sp[lbase + p];
        g_area[gibase + p]  = cv & 0xFFFFu;
        g_perim[gibase + p] = cv >> 16;
    }
}

// global unions only across tile faces (run-pruned + pair-dedup)
__global__ void k_xmerge() {
    int w = blockIdx.x * blockDim.x + threadIdx.x;
    unsigned A = g_bits[w];
    if (A == 0u) return;
    int k = w & 7;
    int row = w >> 3;
    int y = row & (HH - 1);
    int z = row >> 8;
    int base = w << 5;

    bool yb0 = (y & 7) == 0;
    bool yb7 = (y & 7) == 7;
    bool zb0 = (z & 7) == 0;
    bool cross[4] = { yb0, yb0 || zb0, zb0, yb7 || zb0 };
    if (!(cross[0] | cross[1] | cross[2] | cross[3])) return;

    unsigned Al = (k > 0) ? g_bits[w - 1] : 0u;
    unsigned Ar = (k < 7) ? g_bits[w + 1] : 0u;
    unsigned shlA = (A << 1) | (Al >> 31);
    unsigned shrA = (A >> 1) | (Ar << 31);

    int lpa = -1, lpb = -1;

    const int dys[4] = { -1, -1, 0, 1 };
    const int dzs[4] = {  0, -1, -1, -1 };
#pragma unroll
    for (int t = 0; t < 4; t++) {
        if (!cross[t]) continue;
        int ny = y + dys[t];
        int nz = z + dzs[t];
        if ((unsigned)ny >= HH || (unsigned)nz >= DD) continue;
        int nw = w + dys[t] * 8 + dzs[t] * 2048;
        unsigned B  = g_bits[nw];
        unsigned Bl = (k > 0) ? g_bits[nw - 1] : 0u;
        unsigned Br = (k < 7) ? g_bits[nw + 1] : 0u;
        unsigned AB  = A & B;
        unsigned ABl = Al & Bl;
        unsigned shlAB = (AB << 1) | (ABl >> 31);
        unsigned shlB  = (B << 1) | (Bl >> 31);
        unsigned shrB  = (B >> 1) | (Br << 31);

        unsigned Vn  = AB & ~shlAB;
        unsigned DLn = A & ~shlA & shlB & ~B;
        unsigned DRn = A & ~shrA & shrB & ~B;

        int nbase = nw << 5;
#define GEDGE(aa, bb)                                                     \
        { int pa = pload(aa), pb = pload(bb);                             \
          if (pa != lpa || pb != lpb) { lpa = pa; lpb = pb;               \
              uf_union(pa, pb); } }
        while (Vn)  { int p = __ffs(Vn)  - 1; Vn  &= Vn  - 1; GEDGE(base + p, nbase + p); }
        while (DLn) { int p = __ffs(DLn) - 1; DLn &= DLn - 1; GEDGE(base + p, nbase + p - 1); }
        while (DRn) { int p = __ffs(DRn) - 1; DRn &= DRn - 1; GEDGE(base + p, nbase + p + 1); }
#undef GEDGE
    }
}

// sparse: forward non-final tile-root counts to final roots
__global__ void k_push() {
    int i = blockIdx.x * blockDim.x + threadIdx.x;
    if (i >= g_nroots) return;
    int r = g_roots[i];
    int fr = uf_find(r);
    if (fr != r) {
        atomicAdd(&g_area[fr],  g_area[r]);
        atomicAdd(&g_perim[fr], g_perim[r]);
    }
}

// sparse: final roots contribute
__global__ void k_reduce() {
    int i = blockIdx.x * blockDim.x + threadIdx.x;
    float c = 0.0f;
    if (i < g_nroots) {
        int r = g_roots[i];
        if (pload(r) == r) {
            float a = (float)g_area[r];
            float p = (float)g_perim[r];
            c = FOUR_PI * a / (p * p + EPSF);
        }
    }
#pragma unroll
    for (int d = 16; d; d >>= 1)
        c += __shfl_xor_sync(0xffffffffu, c, d);
    if ((threadIdx.x & 31) == 0 && c != 0.0f) atomicAdd(&g_acc, c);
}

__global__ void k_final(float* __restrict__ out) {
    float comp = g_acc * (1.0f / (float)DD);
    out[0] = 1.0f / (comp + EPSF);
}

extern "C" void kernel_launch(void* const* d_in, const int* in_sizes, int n_in,
                              void* d_out, int out_size) {
    const float4* y4 = (const float4*)d_in[0];
    float* out = (float*)d_out;
    const int threads = 256;

    cudaFuncSetAttribute(k_local, cudaFuncAttributeMaxDynamicSharedMemorySize, SMEM_BYTES);

    k_init<<<(NVOX / 4) / threads, threads>>>(y4);
    k_local<<<NTILES, 1024, SMEM_BYTES>>>();
    k_xmerge<<<NWORD / threads, threads>>>();
    k_push<<<2176, threads>>>();     // covers max possible roots (524288) with margin
    k_reduce<<<2176, threads>>>();
    k_final<<<1, 1>>>(out);
}

// round 7
// speedup vs baseline: 5.2077x; 1.0419x over previous
#include <cuda_runtime.h>
#include <cuda_bf16.h>
#include <cstdint>

#define DD 64
#define HH 256
#define WW 256
#define NVOX (DD*HH*WW)
#define NWORD (NVOX/32)          // 131072 ; 8 words/row, 2048 words/z-plane
#define EPSF 1e-5f
#define FOUR_PI 12.566370614359172f

// tile = 256(x) x 8(y) x 8(z) = 16384 voxels, 512 words
#define TY 8
#define TZ 8
#define TVOX 16384
#define TWORDS 512
#define NTILES 256               // 32 y-tiles * 8 z-tiles
#define SMEM_BYTES (TVOX*4 + TWORDS*4 + TWORDS*4)   // parents + bits + bnd = 68KB
#define MAXROOTS 600000

__device__ int           g_parent[NVOX];
__device__ unsigned int  g_area[NVOX];
__device__ unsigned int  g_perim[NVOX];
__device__ unsigned int  g_bits[NWORD];
__device__ int           g_roots[MAXROOTS];
__device__ int           g_nroots;
__device__ float         g_acc;

// ---------- global union-find (ECL-CC style: atomicMin hooking, monotone) ----------
__device__ __forceinline__ int pload(int i) { return __ldcg(&g_parent[i]); }

__device__ __forceinline__ int uf_find(int i) {
    while (true) {
        int p = pload(i);
        if (p == i) return i;
        int gp = pload(p);
        if (gp == p) return p;
        atomicMin(&g_parent[i], gp);     // monotone halving
        i = gp;
    }
}

__device__ __forceinline__ void uf_union(int a, int b) {
    int ra = uf_find(a);
    int rb = uf_find(b);
    while (ra != rb) {
        if (rb > ra) { int t = ra; ra = rb; rb = t; }   // ra > rb
        int old = atomicMin(&g_parent[ra], rb);
        if (old == ra) return;          // was root: linked
        if (old == rb) return;
        if (old < rb) { ra = rb; rb = old; }
        else          { ra = old; }
    }
}

// ---------- shared-memory union-find (same scheme) ----------
__device__ __forceinline__ int sread(int* sp, int i) { return ((volatile int*)sp)[i]; }

__device__ __forceinline__ int luf_find(int* sp, int i) {
    while (true) {
        int p = sread(sp, i);
        if (p == i) return i;
        int gp = sread(sp, p);
        if (gp == p) return p;
        atomicMin(&sp[i], gp);
        i = gp;
    }
}

__device__ __forceinline__ void luf_union(int* sp, int a, int b) {
    int ra = luf_find(sp, a);
    int rb = luf_find(sp, b);
    while (ra != rb) {
        if (rb > ra) { int t = ra; ra = rb; rb = t; }
        int old = atomicMin(&sp[ra], rb);
        if (old == ra) return;
        if (old == rb) return;
        if (old < rb) { ra = rb; rb = old; }
        else          { ra = old; }
    }
}

// ---------------- kernels ----------------

__global__ void k_init(const float4* __restrict__ y4) {
    int t = blockIdx.x * blockDim.x + threadIdx.x;      // NVOX/4 threads
    float4 v = y4[t];
    unsigned nib = (unsigned)(v.x > 0.5f)
                 | ((unsigned)(v.y > 0.5f) << 1)
                 | ((unsigned)(v.z > 0.5f) << 2)
                 | ((unsigned)(v.w > 0.5f) << 3);
    unsigned val = nib << (4 * (threadIdx.x & 7));
#pragma unroll
    for (int d = 1; d < 8; d <<= 1)
        val |= __shfl_xor_sync(0xffffffffu, val, d);
    if ((threadIdx.x & 7) == 0) g_bits[t >> 3] = val;
    if (t == 0) { g_acc = 0.0f; g_nroots = 0; }
}

// fused: per-tile UF + inline 18-conn boundary + per-root counting
__global__ void __launch_bounds__(1024) k_local() {
    extern __shared__ char smraw[];
    int*      sp    = (int*)smraw;
    unsigned* sbits = (unsigned*)(smraw + TVOX * 4);
    unsigned* sbnd  = (unsigned*)(smraw + TVOX * 4 + TWORDS * 4);

    int tid  = threadIdx.x;
    int wid2 = tid >> 1;                   // word 0..511
    int half = tid & 1;
    int wk = wid2 & 7;
    int wy = (wid2 >> 3) & 7;
    int wz = wid2 >> 6;
    int ty = blockIdx.x & 31;
    int tz = blockIdx.x >> 5;
    int gy = (ty << 3) + wy;
    int gz = (tz << 3) + wz;
    int gw = (gz << 11) + (gy << 3) + wk;
    int lbase = wid2 << 5;

    unsigned A = g_bits[gw];

    if (half == 1) {
        sbits[wid2] = A;
        unsigned Alg = (wk > 0) ? g_bits[gw - 1] : 0u;
        unsigned linked = A & ((A << 1) | (Alg >> 31));
#pragma unroll
        for (int p = 0; p < 32; p++)
            sp[lbase + p] = ((linked >> p) & 1u) ? lbase + p - 1 : lbase + p;
    } else {
        // inline boundary (18-neigh erosion, reflect padding) -> sbnd
        unsigned bw = 0u;
        if (A) {
            int ym = (gy == 0)      ? 1      : gy - 1;
            int yp = (gy == HH - 1) ? HH - 2 : gy + 1;
            int zm = (gz == 0)      ? 1      : gz - 1;
            int zp = (gz == DD - 1) ? DD - 2 : gz + 1;
            unsigned ero = 0xffffffffu;
            {
                unsigned l = (wk > 0) ? g_bits[gw - 1] : 0u;
                unsigned r = (wk < 7) ? g_bits[gw + 1] : 0u;
                unsigned shl = (A << 1) | (l >> 31);
                unsigned shr = (A >> 1) | (r << 31);
                if (wk == 0) shl |= (A >> 1) & 1u;
                if (wk == 7) shr |= ((A >> 30) & 1u) << 31;
                ero &= shl & shr;
            }
            int eys[4] = { ym, yp, gy, gy };
            int ezs[4] = { gz, gz, zm, zp };
#pragma unroll
            for (int t = 0; t < 4; t++) {
                int rw = (ezs[t] << 11) + (eys[t] << 3) + wk;
                unsigned cc = g_bits[rw];
                unsigned ll = (wk > 0) ? g_bits[rw - 1] : 0u;
                unsigned rr = (wk < 7) ? g_bits[rw + 1] : 0u;
                unsigned s1 = (cc << 1) | (ll >> 31);
                unsigned s2 = (cc >> 1) | (rr << 31);
                if (wk == 0) s1 |= (cc >> 1) & 1u;
                if (wk == 7) s2 |= ((cc >> 30) & 1u) << 31;
                ero &= cc & s1 & s2;
            }
            int cys[4] = { ym, yp, ym, yp };
            int czs[4] = { zm, zm, zp, zp };
#pragma unroll
            for (int t = 0; t < 4; t++)
                ero &= g_bits[(czs[t] << 11) + (cys[t] << 3) + wk];
            bw = A & ~ero;
        }
        sbnd[wid2] = bw;
    }
    __syncthreads();

    // union phase: 2 directions per thread, run-pruned + pair-dedup
    if (A) {
        unsigned Al = (wk > 0) ? sbits[wid2 - 1] : 0u;
        unsigned Ar = (wk < 7) ? sbits[wid2 + 1] : 0u;
        unsigned shlA = (A << 1) | (Al >> 31);
        unsigned shrA = (A >> 1) | (Ar << 31);

        int lpa = -1, lpb = -1;

        const int dys[4] = { -1, -1, 0, 1 };
        const int dzs[4] = {  0, -1, -1, -1 };
        for (int t = half; t < 4; t += 2) {
            int ny = wy + dys[t];
            int nz = wz + dzs[t];
            if ((unsigned)ny >= TY || (unsigned)nz >= TZ) continue;
            int nwl = wid2 + dys[t] * 8 + dzs[t] * 64;
            unsigned B  = sbits[nwl];
            unsigned Bl = (wk > 0) ? sbits[nwl - 1] : 0u;
            unsigned Br = (wk < 7) ? sbits[nwl + 1] : 0u;
            unsigned AB  = A & B;
            unsigned ABl = Al & Bl;
            unsigned shlAB = (AB << 1) | (ABl >> 31);
            unsigned shlB  = (B << 1) | (Bl >> 31);
            unsigned shrB  = (B >> 1) | (Br << 31);

            unsigned Vn  = AB & ~shlAB;
            unsigned DLn = A & ~shlA & shlB & ~B;
            unsigned DRn = A & ~shrA & shrB & ~B;

            int nbase = nwl << 5;
#define LEDGE(aa, bb)                                                     \
            { int pa = sread(sp, aa), pb = sread(sp, bb);                 \
              if (pa != pb && (pa != lpa || pb != lpb)) {                 \
                  lpa = pa; lpb = pb; luf_union(sp, pa, pb); } }
            while (Vn)  { int p = __ffs(Vn)  - 1; Vn  &= Vn  - 1; LEDGE(lbase + p, nbase + p); }
            while (DLn) { int p = __ffs(DLn) - 1; DLn &= DLn - 1; LEDGE(lbase + p, nbase + p - 1); }
            while (DRn) { int p = __ffs(DRn) - 1; DRn &= DRn - 1; LEDGE(lbase + p, nbase + p + 1); }
#undef LEDGE
        }
    }
    __syncthreads();

    // phase 1: full compression + face/root global parent writes
    unsigned mymask = half ? 0xFFFF0000u : 0x0000FFFFu;
    unsigned m = A & mymask;
    unsigned rootmask = 0u;
    int gibase = (gz << 16) | (gy << 8) | (wk << 5);
    bool isface = (wy == 0) | (wy == TY - 1) | (wz == 0) | (wz == TZ - 1);
    while (m) {
        int p = __ffs(m) - 1; m &= m - 1;
        int v = lbase + p;
        int r = luf_find(sp, v);
        sp[v] = r;                          // post-sync single-writer: plain store ok
        if (r == v) {
            rootmask |= 1u << p;
            g_parent[gibase + p] = gibase + p;
        } else if (isface) {
            int rx = r & 255, ry = (r >> 8) & 7, rz = r >> 11;
            g_parent[gibase + p] =
                (((tz << 3) + rz) << 16) | (((ty << 3) + ry) << 8) | rx;
        }
    }

    // warp-aggregated root-list append (one global atomic per warp)
    {
        int nr = __popc(rootmask);
        int lane = tid & 31;
        int off = nr;
#pragma unroll
        for (int d = 1; d < 32; d <<= 1) {
            int nn = __shfl_up_sync(0xffffffffu, off, d);
            if (lane >= d) off += nn;
        }
        int total = __shfl_sync(0xffffffffu, off, 31);
        int wbase = 0;
        if (lane == 31 && total > 0) wbase = atomicAdd(&g_nroots, total);
        wbase = __shfl_sync(0xffffffffu, wbase, 31);
        int slot = wbase + off - nr;
        unsigned mr = rootmask;
        while (mr) {
            int p = __ffs(mr) - 1; mr &= mr - 1;
            g_roots[slot++] = gibase + p;
        }
    }
    __syncthreads();

    // phase 2: zero root counters (repurpose sp entries at root indices)
    unsigned mr2 = rootmask;
    while (mr2) { int p = __ffs(mr2) - 1; mr2 &= mr2 - 1; sp[lbase + p] = 0; }
    __syncthreads();

    // phase 3: accumulate packed (perim<<16 | area) with run aggregation
    m = A & mymask;
    if (m) {
        unsigned bw = sbnd[wid2];
        int curr = -1; unsigned accv = 0u;
        while (m) {
            int p = __ffs(m) - 1; m &= m - 1;
            int v = lbase + p;
            int r = ((rootmask >> p) & 1u) ? v : sp[v];
            unsigned add = 1u + (((bw >> p) & 1u) << 16);
            if (r == curr) accv += add;
            else {
                if (curr >= 0) atomicAdd((unsigned*)&sp[curr], accv);
                curr = r; accv = add;
            }
        }
        atomicAdd((unsigned*)&sp[curr], accv);
    }
    __syncthreads();

    // phase 4: root owners publish counts (exclusive -> plain stores)
    mr2 = rootmask;
    while (mr2) {
        int p = __ffs(mr2) - 1; mr2 &= mr2 - 1;
        unsigned cv = (unsigned)sp[lbase + p];
        g_area[gibase + p]  = cv & 0xFFFFu;
        g_perim[gibase + p] = cv >> 16;
    }
}

// global unions only across tile faces (run-pruned + pair-dedup)
__global__ void k_xmerge() {
    int w = blockIdx.x * blockDim.x + threadIdx.x;
    unsigned A = g_bits[w];
    if (A == 0u) return;
    int k = w & 7;
    int row = w >> 3;
    int y = row & (HH - 1);
    int z = row >> 8;
    int base = w << 5;

    bool yb0 = (y & 7) == 0;
    bool yb7 = (y & 7) == 7;
    bool zb0 = (z & 7) == 0;
    bool cross[4] = { yb0, yb0 || zb0, zb0, yb7 || zb0 };
    if (!(cross[0] | cross[1] | cross[2] | cross[3])) return;

    unsigned Al = (k > 0) ? g_bits[w - 1] : 0u;
    unsigned Ar = (k < 7) ? g_bits[w + 1] : 0u;
    unsigned shlA = (A << 1) | (Al >> 31);
    unsigned shrA = (A >> 1) | (Ar << 31);

    int lpa = -1, lpb = -1;

    const int dys[4] = { -1, -1, 0, 1 };
    const int dzs[4] = {  0, -1, -1, -1 };
#pragma unroll
    for (int t = 0; t < 4; t++) {
        if (!cross[t]) continue;
        int ny = y + dys[t];
        int nz = z + dzs[t];
        if ((unsigned)ny >= HH || (unsigned)nz >= DD) continue;
        int nw = w + dys[t] * 8 + dzs[t] * 2048;
        unsigned B  = g_bits[nw];
        unsigned Bl = (k > 0) ? g_bits[nw - 1] : 0u;
        unsigned Br = (k < 7) ? g_bits[nw + 1] : 0u;
        unsigned AB  = A & B;
        unsigned ABl = Al & Bl;
        unsigned shlAB = (AB << 1) | (ABl >> 31);
        unsigned shlB  = (B << 1) | (Bl >> 31);
        unsigned shrB  = (B >> 1) | (Br << 31);

        unsigned Vn  = AB & ~shlAB;
        unsigned DLn = A & ~shlA & shlB & ~B;
        unsigned DRn = A & ~shrA & shrB & ~B;

        int nbase = nw << 5;
#define GEDGE(aa, bb)                                                     \
        { int pa = pload(aa), pb = pload(bb);                             \
          if (pa != pb && (pa != lpa || pb != lpb)) {                     \
              lpa = pa; lpb = pb; uf_union(pa, pb); } }
        while (Vn)  { int p = __ffs(Vn)  - 1; Vn  &= Vn  - 1; GEDGE(base + p, nbase + p); }
        while (DLn) { int p = __ffs(DLn) - 1; DLn &= DLn - 1; GEDGE(base + p, nbase + p - 1); }
        while (DRn) { int p = __ffs(DRn) - 1; DRn &= DRn - 1; GEDGE(base + p, nbase + p + 1); }
#undef GEDGE
    }
}

// sparse: forward non-final tile-root counts to final roots (stride loop)
__global__ void k_push() {
    int n = g_nroots;
    for (int i = blockIdx.x * blockDim.x + threadIdx.x; i < n;
         i += gridDim.x * blockDim.x) {
        int r = g_roots[i];
        int fr = uf_find(r);
        if (fr != r) {
            atomicAdd(&g_area[fr],  g_area[r]);
            atomicAdd(&g_perim[fr], g_perim[r]);
        }
    }
}

// sparse: final roots contribute (stride loop)
__global__ void k_reduce() {
    int n = g_nroots;
    float c = 0.0f;
    for (int i = blockIdx.x * blockDim.x + threadIdx.x; i < n;
         i += gridDim.x * blockDim.x) {
        int r = g_roots[i];
        if (pload(r) == r) {
            float a = (float)g_area[r];
            float p = (float)g_perim[r];
            c += FOUR_PI * a / (p * p + EPSF);
        }
    }
#pragma unroll
    for (int d = 16; d; d >>= 1)
        c += __shfl_xor_sync(0xffffffffu, c, d);
    if ((threadIdx.x & 31) == 0 && c != 0.0f) atomicAdd(&g_acc, c);
}

__global__ void k_final(float* __restrict__ out) {
    float comp = g_acc * (1.0f / (float)DD);
    out[0] = 1.0f / (comp + EPSF);
}

extern "C" void kernel_launch(void* const* d_in, const int* in_sizes, int n_in,
                              void* d_out, int out_size) {
    const float4* y4 = (const float4*)d_in[0];
    float* out = (float*)d_out;
    const int threads = 256;

    cudaFuncSetAttribute(k_local, cudaFuncAttributeMaxDynamicSharedMemorySize, SMEM_BYTES);

    k_init<<<(NVOX / 4) / threads, threads>>>(y4);
    k_local<<<NTILES, 1024, SMEM_BYTES>>>();
    k_xmerge<<<NWORD / threads, threads>>>();
    k_push<<<264, threads>>>();
    k_reduce<<<264, threads>>>();
    k_final<<<1, 1>>>(out);
}